// round 1
// baseline (speedup 1.0000x reference)
#include <cuda_runtime.h>
#include <cuda_bf16.h>
#include <math.h>

// Problem dims (fixed by reference)
#define MTOK   4096        // B*N = 2*2048
#define WIDTH  1024
#define HEADS  16
#define HDIM   64
#define HIDDEN 4096
#define SEQ    2048

// ---------------------------------------------------------------------------
// Scratch (device globals; no allocation allowed)
// ---------------------------------------------------------------------------
__device__ float g_h   [MTOK * WIDTH];    // LN output (reused for ln1 & ln2)
__device__ float g_qkv [MTOK * 3 * WIDTH];
__device__ float g_attn[MTOK * WIDTH];    // attention output (pre-proj)
__device__ float g_x1  [MTOK * WIDTH];    // x + attn proj (residual 1)
__device__ float g_fc1 [MTOK * HIDDEN];

// ---------------------------------------------------------------------------
// LayerNorm: one block per row of 1024, 256 threads, float4 per thread
// ---------------------------------------------------------------------------
__device__ __forceinline__ float warp_sum(float v) {
    #pragma unroll
    for (int o = 16; o > 0; o >>= 1) v += __shfl_xor_sync(0xffffffffu, v, o);
    return v;
}

__global__ void ln_kernel(const float* __restrict__ x,
                          const float* __restrict__ g,
                          const float* __restrict__ b,
                          float* __restrict__ out) {
    int row = blockIdx.x;
    int t   = threadIdx.x;
    const float4* xr = reinterpret_cast<const float4*>(x + (size_t)row * WIDTH);
    float4 v = xr[t];
    float s  = v.x + v.y + v.z + v.w;
    float ss = v.x*v.x + v.y*v.y + v.z*v.z + v.w*v.w;

    __shared__ float red_s[8], red_ss[8];
    float ws = warp_sum(s), wss = warp_sum(ss);
    int wid = t >> 5, lid = t & 31;
    if (lid == 0) { red_s[wid] = ws; red_ss[wid] = wss; }
    __syncthreads();
    if (wid == 0) {
        float a  = (lid < 8) ? red_s[lid]  : 0.f;
        float a2 = (lid < 8) ? red_ss[lid] : 0.f;
        a  = warp_sum(a);
        a2 = warp_sum(a2);
        if (lid == 0) { red_s[0] = a; red_ss[0] = a2; }
    }
    __syncthreads();
    float mu  = red_s[0]  * (1.0f / WIDTH);
    float var = red_ss[0] * (1.0f / WIDTH) - mu * mu;
    float rs  = rsqrtf(var + 1e-5f);

    const float4* g4 = reinterpret_cast<const float4*>(g);
    const float4* b4 = reinterpret_cast<const float4*>(b);
    float4 gg = g4[t], bb = b4[t];
    float4 o;
    o.x = (v.x - mu) * rs * gg.x + bb.x;
    o.y = (v.y - mu) * rs * gg.y + bb.y;
    o.z = (v.z - mu) * rs * gg.z + bb.z;
    o.w = (v.w - mu) * rs * gg.w + bb.w;
    reinterpret_cast<float4*>(out + (size_t)row * WIDTH)[t] = o;
}

// ---------------------------------------------------------------------------
// SGEMM: C[M,N] = A[M,K] @ B[K,N]  (+ epilogue)
// BM=BN=128, BK=8, TM=TN=8, 256 threads. All dims divide tiles exactly.
// OP: 0 = none, 1 = +bias +residual, 2 = gelu(+bias)
// ---------------------------------------------------------------------------
__device__ __forceinline__ float gelu_exact(float x) {
    return 0.5f * x * (1.0f + erff(x * 0.7071067811865476f));
}

template <int OP>
__global__ void __launch_bounds__(256)
sgemm_kernel(int M, int N, int K,
             const float* __restrict__ A,
             const float* __restrict__ B,
             const float* __restrict__ bias,
             const float* __restrict__ res,
             float* __restrict__ C) {
    __shared__ float As[8][128];
    __shared__ float Bs[8][128];

    const int tid  = threadIdx.x;
    const int cRow = blockIdx.y;
    const int cCol = blockIdx.x;

    const int threadCol = tid & 15;   // 0..15
    const int threadRow = tid >> 4;   // 0..15

    const float* Ab = A + (size_t)cRow * 128 * K;
    const float* Bb = B + (size_t)cCol * 128;

    const int innerRowA = tid >> 1;          // 0..127
    const int innerColA = (tid & 1) * 4;     // 0 or 4
    const int innerRowB = tid >> 5;          // 0..7
    const int innerColB = (tid & 31) * 4;    // 0..124

    float acc[8][8];
    #pragma unroll
    for (int i = 0; i < 8; i++)
        #pragma unroll
        for (int j = 0; j < 8; j++) acc[i][j] = 0.f;

    float regM[8], regN[8];

    for (int kb = 0; kb < K; kb += 8) {
        float4 a = *reinterpret_cast<const float4*>(Ab + (size_t)innerRowA * K + kb + innerColA);
        As[innerColA + 0][innerRowA] = a.x;
        As[innerColA + 1][innerRowA] = a.y;
        As[innerColA + 2][innerRowA] = a.z;
        As[innerColA + 3][innerRowA] = a.w;
        *reinterpret_cast<float4*>(&Bs[innerRowB][innerColB]) =
            *reinterpret_cast<const float4*>(Bb + (size_t)(kb + innerRowB) * N + innerColB);
        __syncthreads();

        #pragma unroll
        for (int k = 0; k < 8; k++) {
            float4 m0 = *reinterpret_cast<const float4*>(&As[k][threadRow * 8 + 0]);
            float4 m1 = *reinterpret_cast<const float4*>(&As[k][threadRow * 8 + 4]);
            float4 n0 = *reinterpret_cast<const float4*>(&Bs[k][threadCol * 8 + 0]);
            float4 n1 = *reinterpret_cast<const float4*>(&Bs[k][threadCol * 8 + 4]);
            regM[0]=m0.x; regM[1]=m0.y; regM[2]=m0.z; regM[3]=m0.w;
            regM[4]=m1.x; regM[5]=m1.y; regM[6]=m1.z; regM[7]=m1.w;
            regN[0]=n0.x; regN[1]=n0.y; regN[2]=n0.z; regN[3]=n0.w;
            regN[4]=n1.x; regN[5]=n1.y; regN[6]=n1.z; regN[7]=n1.w;
            #pragma unroll
            for (int i = 0; i < 8; i++)
                #pragma unroll
                for (int j = 0; j < 8; j++)
                    acc[i][j] = fmaf(regM[i], regN[j], acc[i][j]);
        }
        __syncthreads();
    }

    const int rowBase = cRow * 128 + threadRow * 8;
    const int colBase = cCol * 128 + threadCol * 8;

    #pragma unroll
    for (int i = 0; i < 8; i++) {
        const int row = rowBase + i;
        #pragma unroll
        for (int j4 = 0; j4 < 8; j4 += 4) {
            const int col = colBase + j4;
            float4 v = make_float4(acc[i][j4+0], acc[i][j4+1], acc[i][j4+2], acc[i][j4+3]);
            if (OP == 1) {
                float4 bi = *reinterpret_cast<const float4*>(bias + col);
                float4 rr = *reinterpret_cast<const float4*>(res + (size_t)row * N + col);
                v.x += bi.x + rr.x; v.y += bi.y + rr.y;
                v.z += bi.z + rr.z; v.w += bi.w + rr.w;
            } else if (OP == 2) {
                float4 bi = *reinterpret_cast<const float4*>(bias + col);
                v.x = gelu_exact(v.x + bi.x);
                v.y = gelu_exact(v.y + bi.y);
                v.z = gelu_exact(v.z + bi.z);
                v.w = gelu_exact(v.w + bi.w);
            }
            *reinterpret_cast<float4*>(C + (size_t)row * N + col) = v;
        }
    }
}

// ---------------------------------------------------------------------------
// Flash attention (fp32, online softmax)
// grid = (N/64 = 32 query blocks, B*H = 32), block = 256 threads
// qkv layout: [tok, 3*1024] with col = s*1024 + h*64 + d
// Shared tiles (dynamic): Qt[d][q], Kt[d][k], V[k][d], St[k][q], all [64][68]
// ---------------------------------------------------------------------------
#define TPAD 68
#define ATTN_SMEM_BYTES ((4 * 64 * TPAD + 3 * 64) * 4)

__global__ void __launch_bounds__(256)
attn_kernel(const float* __restrict__ qkv, float* __restrict__ out) {
    extern __shared__ float smem[];
    float* Qt   = smem;                    // [64][TPAD]  (dim-major)
    float* Kt   = Qt + 64 * TPAD;          // [64][TPAD]  (dim-major)
    float* Vs   = Kt + 64 * TPAD;          // [64][TPAD]  (key-major)
    float* St   = Vs + 64 * TPAD;          // [64][TPAD]  St[key][query]
    float* m_sh = St + 64 * TPAD;          // [64]
    float* l_sh = m_sh + 64;               // [64]
    float* c_sh = l_sh + 64;               // [64]

    const int t  = threadIdx.x;
    const int qb = blockIdx.x;             // query block (0..31)
    const int bh = blockIdx.y;             // b*16 + h
    const int bb = bh >> 4;
    const int h  = bh & 15;
    const int tok0 = bb * SEQ;

    const int tx = t & 15;                 // 0..15
    const int ty = t >> 4;                 // 0..15

    // ---- Load Q tile transposed: Qt[d][q] ----
    {
        const int r  = t >> 2;                 // query row 0..63
        const int c0 = (t & 3) * 16;           // dim start
        const int tokq = tok0 + qb * 64 + r;
        #pragma unroll
        for (int i = 0; i < 4; i++) {
            int c = c0 + i * 4;
            float4 v = *reinterpret_cast<const float4*>(
                qkv + (size_t)tokq * 3072 + h * 64 + c);
            Qt[(c + 0) * TPAD + r] = v.x;
            Qt[(c + 1) * TPAD + r] = v.y;
            Qt[(c + 2) * TPAD + r] = v.z;
            Qt[(c + 3) * TPAD + r] = v.w;
        }
    }
    if (t < 64) { m_sh[t] = -INFINITY; l_sh[t] = 0.f; }

    float oacc[4][4];
    #pragma unroll
    for (int i = 0; i < 4; i++)
        #pragma unroll
        for (int j = 0; j < 4; j++) oacc[i][j] = 0.f;

    const float scale = 0.125f;   // 1/sqrt(64)

    for (int kb = 0; kb < SEQ / 64; kb++) {
        __syncthreads();   // protect K/V/St reuse from previous iteration

        // ---- Load K (transposed) and V (row-major) tiles ----
        {
            const int r  = t >> 2;
            const int c0 = (t & 3) * 16;
            const int tokk = tok0 + kb * 64 + r;
            const float* kptr = qkv + (size_t)tokk * 3072 + 1024 + h * 64;
            const float* vptr = qkv + (size_t)tokk * 3072 + 2048 + h * 64;
            #pragma unroll
            for (int i = 0; i < 4; i++) {
                int c = c0 + i * 4;
                float4 kv = *reinterpret_cast<const float4*>(kptr + c);
                Kt[(c + 0) * TPAD + r] = kv.x;
                Kt[(c + 1) * TPAD + r] = kv.y;
                Kt[(c + 2) * TPAD + r] = kv.z;
                Kt[(c + 3) * TPAD + r] = kv.w;
                float4 vv = *reinterpret_cast<const float4*>(vptr + c);
                *reinterpret_cast<float4*>(Vs + r * TPAD + c) = vv;
            }
        }
        __syncthreads();

        // ---- S = Q K^T : thread owns queries 4*ty..+3, keys 4*tx..+3 ----
        float sacc[4][4];
        #pragma unroll
        for (int i = 0; i < 4; i++)
            #pragma unroll
            for (int j = 0; j < 4; j++) sacc[i][j] = 0.f;

        #pragma unroll 4
        for (int d = 0; d < 64; d++) {
            float4 q = *reinterpret_cast<const float4*>(Qt + d * TPAD + 4 * ty);
            float4 k = *reinterpret_cast<const float4*>(Kt + d * TPAD + 4 * tx);
            float qa[4] = {q.x, q.y, q.z, q.w};
            float ka[4] = {k.x, k.y, k.z, k.w};
            #pragma unroll
            for (int i = 0; i < 4; i++)
                #pragma unroll
                for (int j = 0; j < 4; j++)
                    sacc[i][j] = fmaf(qa[i], ka[j], sacc[i][j]);
        }
        // store S transposed: St[key][query], scaled
        #pragma unroll
        for (int j = 0; j < 4; j++) {
            float4 p = make_float4(sacc[0][j] * scale, sacc[1][j] * scale,
                                   sacc[2][j] * scale, sacc[3][j] * scale);
            *reinterpret_cast<float4*>(St + (4 * tx + j) * TPAD + 4 * ty) = p;
        }
        __syncthreads();

        // ---- online softmax stats: thread r handles query row r ----
        if (t < 64) {
            const int r = t;
            float mx = -INFINITY;
            #pragma unroll 8
            for (int j = 0; j < 64; j++) mx = fmaxf(mx, St[j * TPAD + r]);
            float mold = m_sh[r];
            float mnew = fmaxf(mold, mx);
            float corr = __expf(mold - mnew);
            float s = 0.f;
            #pragma unroll 8
            for (int j = 0; j < 64; j++) {
                float p = __expf(St[j * TPAD + r] - mnew);
                St[j * TPAD + r] = p;
                s += p;
            }
            l_sh[r] = l_sh[r] * corr + s;
            m_sh[r] = mnew;
            c_sh[r] = corr;
        }
        __syncthreads();

        // ---- O = O*corr + P V : thread owns queries 4*ty..+3, dims 4*tx..+3 ----
        #pragma unroll
        for (int i = 0; i < 4; i++) {
            float c = c_sh[4 * ty + i];
            #pragma unroll
            for (int j = 0; j < 4; j++) oacc[i][j] *= c;
        }
        #pragma unroll 4
        for (int kk = 0; kk < 64; kk++) {
            float4 p = *reinterpret_cast<const float4*>(St + kk * TPAD + 4 * ty);
            float4 v = *reinterpret_cast<const float4*>(Vs + kk * TPAD + 4 * tx);
            float pa[4] = {p.x, p.y, p.z, p.w};
            float va[4] = {v.x, v.y, v.z, v.w};
            #pragma unroll
            for (int i = 0; i < 4; i++)
                #pragma unroll
                for (int j = 0; j < 4; j++)
                    oacc[i][j] = fmaf(pa[i], va[j], oacc[i][j]);
        }
    }
    __syncthreads();

    // ---- write out: out[tok][h*64 + d] ----
    #pragma unroll
    for (int i = 0; i < 4; i++) {
        const int q   = 4 * ty + i;
        const int tok = tok0 + qb * 64 + q;
        const float inv = 1.0f / l_sh[q];
        float4 o = make_float4(oacc[i][0] * inv, oacc[i][1] * inv,
                               oacc[i][2] * inv, oacc[i][3] * inv);
        *reinterpret_cast<float4*>(out + (size_t)tok * WIDTH + h * 64 + 4 * tx) = o;
    }
}

// ---------------------------------------------------------------------------
// Launch
// ---------------------------------------------------------------------------
extern "C" void kernel_launch(void* const* d_in, const int* in_sizes, int n_in,
                              void* d_out, int out_size) {
    const float* x      = (const float*)d_in[0];
    const float* ln1_g  = (const float*)d_in[1];
    const float* ln1_b  = (const float*)d_in[2];
    const float* w_qkv  = (const float*)d_in[3];
    const float* w_proj = (const float*)d_in[4];
    const float* b_proj = (const float*)d_in[5];
    const float* ln2_g  = (const float*)d_in[6];
    const float* ln2_b  = (const float*)d_in[7];
    const float* w_fc1  = (const float*)d_in[8];
    const float* b_fc1  = (const float*)d_in[9];
    const float* w_fc2  = (const float*)d_in[10];
    const float* b_fc2  = (const float*)d_in[11];
    float* out = (float*)d_out;

    void *ph, *pqkv, *pattn, *px1, *pfc1;
    cudaGetSymbolAddress(&ph,    g_h);
    cudaGetSymbolAddress(&pqkv,  g_qkv);
    cudaGetSymbolAddress(&pattn, g_attn);
    cudaGetSymbolAddress(&px1,   g_x1);
    cudaGetSymbolAddress(&pfc1,  g_fc1);
    float* hbuf  = (float*)ph;
    float* qkvb  = (float*)pqkv;
    float* attnb = (float*)pattn;
    float* x1b   = (float*)px1;
    float* fc1b  = (float*)pfc1;

    cudaFuncSetAttribute(attn_kernel,
                         cudaFuncAttributeMaxDynamicSharedMemorySize,
                         ATTN_SMEM_BYTES);

    // 1) LN1
    ln_kernel<<<MTOK, 256>>>(x, ln1_g, ln1_b, hbuf);

    // 2) qkv = h @ w_qkv   [4096,1024]@[1024,3072]
    {
        dim3 grid(3 * WIDTH / 128, MTOK / 128);
        sgemm_kernel<0><<<grid, 256>>>(MTOK, 3 * WIDTH, WIDTH,
                                       hbuf, w_qkv, nullptr, nullptr, qkvb);
    }

    // 3) attention
    {
        dim3 grid(SEQ / 64, 2 * HEADS);
        attn_kernel<<<grid, 256, ATTN_SMEM_BYTES>>>(qkvb, attnb);
    }

    // 4) x1 = x + attn @ w_proj + b_proj
    {
        dim3 grid(WIDTH / 128, MTOK / 128);
        sgemm_kernel<1><<<grid, 256>>>(MTOK, WIDTH, WIDTH,
                                       attnb, w_proj, b_proj, x, x1b);
    }

    // 5) LN2
    ln_kernel<<<MTOK, 256>>>(x1b, ln2_g, ln2_b, hbuf);

    // 6) fc1 = gelu(h @ w_fc1 + b_fc1)
    {
        dim3 grid(HIDDEN / 128, MTOK / 128);
        sgemm_kernel<2><<<grid, 256>>>(MTOK, HIDDEN, WIDTH,
                                       hbuf, w_fc1, b_fc1, nullptr, fc1b);
    }

    // 7) out = x1 + fc1 @ w_fc2 + b_fc2
    {
        dim3 grid(WIDTH / 128, MTOK / 128);
        sgemm_kernel<1><<<grid, 256>>>(MTOK, WIDTH, HIDDEN,
                                       fc1b, w_fc2, b_fc2, x1b, out);
    }
}

// round 2
// speedup vs baseline: 2.8720x; 2.8720x over previous
#include <cuda_runtime.h>
#include <cuda_bf16.h>
#include <math.h>
#include <stdint.h>

// Problem dims (fixed by reference)
#define MTOK   4096        // B*N = 2*2048
#define WIDTH  1024
#define HEADS  16
#define HDIM   64
#define HIDDEN 4096
#define SEQ    2048

// ---------------------------------------------------------------------------
// Scratch (device globals; no allocation allowed)
// ---------------------------------------------------------------------------
__device__ float g_h   [MTOK * WIDTH];
__device__ float g_qkv [MTOK * 3 * WIDTH];
__device__ float g_attn[MTOK * WIDTH];
__device__ float g_x1  [MTOK * WIDTH];
__device__ float g_fc1 [MTOK * HIDDEN];

// ---------------------------------------------------------------------------
// Helpers
// ---------------------------------------------------------------------------
__device__ __forceinline__ float warp_sum(float v) {
    #pragma unroll
    for (int o = 16; o > 0; o >>= 1) v += __shfl_xor_sync(0xffffffffu, v, o);
    return v;
}

// Round-to-nearest fp32 -> tf32 (keeps bit pattern in a float). rna is
// critical: truncation has a -2^-11 bias that accumulates to ~1e-3 rel err.
__device__ __forceinline__ float tf32r(float x) {
    uint32_t u;
    asm("cvt.rna.tf32.f32 %0, %1;" : "=r"(u) : "f"(x));
    return __uint_as_float(u);
}

// D += A*B, m16n8k8 tf32. a,b hold tf32 bit patterns.
__device__ __forceinline__ void mma_tf32(float c[4], const uint32_t a[4], const uint32_t b[2]) {
    asm volatile(
        "mma.sync.aligned.m16n8k8.row.col.f32.tf32.tf32.f32 "
        "{%0,%1,%2,%3}, {%4,%5,%6,%7}, {%8,%9}, {%0,%1,%2,%3};\n"
        : "+f"(c[0]), "+f"(c[1]), "+f"(c[2]), "+f"(c[3])
        : "r"(a[0]), "r"(a[1]), "r"(a[2]), "r"(a[3]),
          "r"(b[0]), "r"(b[1]));
}

__device__ __forceinline__ float gelu_exact(float x) {
    return 0.5f * x * (1.0f + erff(x * 0.7071067811865476f));
}

// ---------------------------------------------------------------------------
// LayerNorm (unchanged from R1: negligible cost)
// ---------------------------------------------------------------------------
__global__ void ln_kernel(const float* __restrict__ x,
                          const float* __restrict__ g,
                          const float* __restrict__ b,
                          float* __restrict__ out) {
    int row = blockIdx.x;
    int t   = threadIdx.x;
    const float4* xr = reinterpret_cast<const float4*>(x + (size_t)row * WIDTH);
    float4 v = xr[t];
    float s  = v.x + v.y + v.z + v.w;
    float ss = v.x*v.x + v.y*v.y + v.z*v.z + v.w*v.w;

    __shared__ float red_s[8], red_ss[8];
    float ws = warp_sum(s), wss = warp_sum(ss);
    int wid = t >> 5, lid = t & 31;
    if (lid == 0) { red_s[wid] = ws; red_ss[wid] = wss; }
    __syncthreads();
    if (wid == 0) {
        float a  = (lid < 8) ? red_s[lid]  : 0.f;
        float a2 = (lid < 8) ? red_ss[lid] : 0.f;
        a  = warp_sum(a);
        a2 = warp_sum(a2);
        if (lid == 0) { red_s[0] = a; red_ss[0] = a2; }
    }
    __syncthreads();
    float mu  = red_s[0]  * (1.0f / WIDTH);
    float var = red_ss[0] * (1.0f / WIDTH) - mu * mu;
    float rs  = rsqrtf(var + 1e-5f);

    const float4* g4 = reinterpret_cast<const float4*>(g);
    const float4* b4 = reinterpret_cast<const float4*>(b);
    float4 gg = g4[t], bb = b4[t];
    float4 o;
    o.x = (v.x - mu) * rs * gg.x + bb.x;
    o.y = (v.y - mu) * rs * gg.y + bb.y;
    o.z = (v.z - mu) * rs * gg.z + bb.z;
    o.w = (v.w - mu) * rs * gg.w + bb.w;
    reinterpret_cast<float4*>(out + (size_t)row * WIDTH)[t] = o;
}

// ---------------------------------------------------------------------------
// TF32 tensor-core GEMM: C[M,N] = A[M,K] @ B[K,N] (+ epilogue)
// BM=BN=128, BK=32, 256 threads = 8 warps (2 warp-rows x 4 warp-cols),
// warp tile 64x32 = 4x4 m16n8k8 tiles. Double-buffered smem, reg staging.
// Smem: As[m][k] stride 36 (frag bank = 4*gr+ctg, conflict-free)
//       Bs[k][n] stride 136 (frag bank = 8*ctg+gr, conflict-free)
// OP: 0 = none, 1 = +bias +residual, 2 = gelu(+bias)
// ---------------------------------------------------------------------------
#define SA 36
#define SB 136
#define AS_FLOATS (128 * SA)   // 4608
#define BS_FLOATS (32 * SB)    // 4352
#define GEMM_SMEM_BYTES ((2 * (AS_FLOATS + BS_FLOATS)) * 4)   // 71680

template <int OP>
__global__ void __launch_bounds__(256)
gemm_tc(int M, int N, int K,
        const float* __restrict__ A,
        const float* __restrict__ B,
        const float* __restrict__ bias,
        const float* __restrict__ res,
        float* __restrict__ C) {
    extern __shared__ float sm[];
    float* AsBase = sm;                    // [2][AS_FLOATS]
    float* BsBase = sm + 2 * AS_FLOATS;    // [2][BS_FLOATS]

    const int tid     = threadIdx.x;
    const int warpId  = tid >> 5;
    const int lane    = tid & 31;
    const int gr      = lane >> 2;    // 0..7
    const int ctg     = lane & 3;     // 0..3
    const int warpRow = warpId >> 2;  // 0..1
    const int warpCol = warpId & 3;   // 0..3

    const int cRow = blockIdx.y;
    const int cCol = blockIdx.x;

    const float* Ablk = A + (size_t)cRow * 128 * K;
    const float* Bblk = B + cCol * 128;

    float acc[4][4][4];
    #pragma unroll
    for (int i = 0; i < 4; i++)
        #pragma unroll
        for (int j = 0; j < 4; j++)
            #pragma unroll
            for (int k = 0; k < 4; k++) acc[i][j][k] = 0.f;

    float4 aReg[4], bReg[4];

    // --- prologue: load chunk 0, convert, store stage 0 ---
    #pragma unroll
    for (int i = 0; i < 4; i++) {
        int aIdx = tid + i * 256;
        aReg[i] = *reinterpret_cast<const float4*>(
            Ablk + (size_t)(aIdx >> 3) * K + ((aIdx & 7) << 2));
        int bIdx = tid + i * 256;
        bReg[i] = *reinterpret_cast<const float4*>(
            Bblk + (size_t)(bIdx >> 5) * N + ((bIdx & 31) << 2));
    }
    #pragma unroll
    for (int i = 0; i < 4; i++) {
        int aIdx = tid + i * 256;
        float4 t = aReg[i];
        *reinterpret_cast<float4*>(&AsBase[(aIdx >> 3) * SA + ((aIdx & 7) << 2)]) =
            make_float4(tf32r(t.x), tf32r(t.y), tf32r(t.z), tf32r(t.w));
        int bIdx = tid + i * 256;
        float4 u = bReg[i];
        *reinterpret_cast<float4*>(&BsBase[(bIdx >> 5) * SB + ((bIdx & 31) << 2)]) =
            make_float4(tf32r(u.x), tf32r(u.y), tf32r(u.z), tf32r(u.w));
    }
    __syncthreads();

    const int nChunk = K >> 5;
    for (int kb = 0; kb < nChunk; kb++) {
        const int cur = kb & 1;
        const float* AsS = AsBase + cur * AS_FLOATS;
        const float* BsS = BsBase + cur * BS_FLOATS;
        const uint32_t* uAs = reinterpret_cast<const uint32_t*>(AsS);
        const uint32_t* uBs = reinterpret_cast<const uint32_t*>(BsS);

        // prefetch next chunk into registers (overlaps with compute below)
        if (kb + 1 < nChunk) {
            const int kOff = (kb + 1) << 5;
            #pragma unroll
            for (int i = 0; i < 4; i++) {
                int aIdx = tid + i * 256;
                aReg[i] = *reinterpret_cast<const float4*>(
                    Ablk + (size_t)(aIdx >> 3) * K + kOff + ((aIdx & 7) << 2));
                int bIdx = tid + i * 256;
                bReg[i] = *reinterpret_cast<const float4*>(
                    Bblk + (size_t)(kOff + (bIdx >> 5)) * N + ((bIdx & 31) << 2));
            }
        }

        // compute 4 k-steps of m16n8k8
        #pragma unroll
        for (int ks = 0; ks < 4; ks++) {
            uint32_t af[4][4];
            #pragma unroll
            for (int mt = 0; mt < 4; mt++) {
                int m0 = warpRow * 64 + mt * 16 + gr;
                const uint32_t* pa = uAs + m0 * SA + ks * 8 + ctg;
                af[mt][0] = pa[0];
                af[mt][1] = pa[8 * SA];
                af[mt][2] = pa[4];
                af[mt][3] = pa[8 * SA + 4];
            }
            uint32_t bf[4][2];
            #pragma unroll
            for (int nt = 0; nt < 4; nt++) {
                int nb = warpCol * 32 + nt * 8 + gr;
                const uint32_t* pb = uBs + (ks * 8 + ctg) * SB + nb;
                bf[nt][0] = pb[0];
                bf[nt][1] = pb[4 * SB];
            }
            #pragma unroll
            for (int mt = 0; mt < 4; mt++)
                #pragma unroll
                for (int nt = 0; nt < 4; nt++)
                    mma_tf32(acc[mt][nt], af[mt], bf[nt]);
        }

        // store next chunk into the other stage
        if (kb + 1 < nChunk) {
            float* AsD = AsBase + (cur ^ 1) * AS_FLOATS;
            float* BsD = BsBase + (cur ^ 1) * BS_FLOATS;
            #pragma unroll
            for (int i = 0; i < 4; i++) {
                int aIdx = tid + i * 256;
                float4 t = aReg[i];
                *reinterpret_cast<float4*>(&AsD[(aIdx >> 3) * SA + ((aIdx & 7) << 2)]) =
                    make_float4(tf32r(t.x), tf32r(t.y), tf32r(t.z), tf32r(t.w));
                int bIdx = tid + i * 256;
                float4 u = bReg[i];
                *reinterpret_cast<float4*>(&BsD[(bIdx >> 5) * SB + ((bIdx & 31) << 2)]) =
                    make_float4(tf32r(u.x), tf32r(u.y), tf32r(u.z), tf32r(u.w));
            }
        }
        __syncthreads();
    }

    // --- epilogue ---
    #pragma unroll
    for (int mt = 0; mt < 4; mt++) {
        #pragma unroll
        for (int rr = 0; rr < 2; rr++) {
            const int row = cRow * 128 + warpRow * 64 + mt * 16 + gr + rr * 8;
            #pragma unroll
            for (int nt = 0; nt < 4; nt++) {
                const int col = cCol * 128 + warpCol * 32 + nt * 8 + 2 * ctg;
                float v0 = acc[mt][nt][rr * 2 + 0];
                float v1 = acc[mt][nt][rr * 2 + 1];
                if (OP == 1) {
                    float2 bi = *reinterpret_cast<const float2*>(bias + col);
                    float2 rv = *reinterpret_cast<const float2*>(res + (size_t)row * N + col);
                    v0 += bi.x + rv.x;
                    v1 += bi.y + rv.y;
                } else if (OP == 2) {
                    float2 bi = *reinterpret_cast<const float2*>(bias + col);
                    v0 = gelu_exact(v0 + bi.x);
                    v1 = gelu_exact(v1 + bi.y);
                }
                *reinterpret_cast<float2*>(C + (size_t)row * N + col) = make_float2(v0, v1);
            }
        }
    }
}

// ---------------------------------------------------------------------------
// Flash attention with TF32 mma.
// Block = 128 threads = 4 warps; 64 queries x 1 head per block.
// Warp w owns query rows [16w, 16w+16): online softmax stats live in regs,
// P tile is warp-private (only __syncwarp between softmax and P@V).
// Smem (stride 68 => all frag loads conflict-free, no transposes):
//   Qs[q][d], Ks[key][d], Vs[key][d], Ps[q][key], each [64][68].
// ---------------------------------------------------------------------------
#define SATT 68
#define ATT_TILE (64 * SATT)
#define ATTN_SMEM_BYTES (4 * ATT_TILE * 4)   // 69632

__global__ void __launch_bounds__(128)
attn_tc(const float* __restrict__ qkv, float* __restrict__ out) {
    extern __shared__ float sm[];
    float* Qs = sm;
    float* Ks = sm + ATT_TILE;
    float* Vs = sm + 2 * ATT_TILE;
    float* Ps = sm + 3 * ATT_TILE;
    const uint32_t* uQ = reinterpret_cast<const uint32_t*>(Qs);
    const uint32_t* uK = reinterpret_cast<const uint32_t*>(Ks);
    const uint32_t* uV = reinterpret_cast<const uint32_t*>(Vs);
    const uint32_t* uP = reinterpret_cast<const uint32_t*>(Ps);

    const int t     = threadIdx.x;
    const int warp  = t >> 5;
    const int lane  = t & 31;
    const int gr    = lane >> 2;
    const int ctg   = lane & 3;
    const int mbase = warp * 16;

    const int qb = blockIdx.x;           // 0..31
    const int bh = blockIdx.y;           // b*16+h
    const int bb = bh >> 4;
    const int h  = bh & 15;
    const int tok0 = bb * SEQ;

    // ---- load Q tile (rna-converted) ----
    #pragma unroll
    for (int i = 0; i < 8; i++) {
        int idx = t + i * 128;
        int row = idx >> 4;
        int c   = (idx & 15) << 2;
        float4 v = *reinterpret_cast<const float4*>(
            qkv + (size_t)(tok0 + qb * 64 + row) * 3072 + h * 64 + c);
        *reinterpret_cast<float4*>(&Qs[row * SATT + c]) =
            make_float4(tf32r(v.x), tf32r(v.y), tf32r(v.z), tf32r(v.w));
    }

    float m0 = -1e30f, m1 = -1e30f, l0 = 0.f, l1 = 0.f;
    float o[8][4];
    #pragma unroll
    for (int nt = 0; nt < 8; nt++)
        #pragma unroll
        for (int k = 0; k < 4; k++) o[nt][k] = 0.f;

    for (int kb = 0; kb < SEQ / 64; kb++) {
        __syncthreads();   // prev iteration's P@V (reads Vs) done; Q visible

        // ---- load K, V tiles ----
        #pragma unroll
        for (int i = 0; i < 8; i++) {
            int idx = t + i * 128;
            int row = idx >> 4;
            int c   = (idx & 15) << 2;
            const float* base = qkv + (size_t)(tok0 + kb * 64 + row) * 3072 + h * 64 + c;
            float4 kv = *reinterpret_cast<const float4*>(base + 1024);
            *reinterpret_cast<float4*>(&Ks[row * SATT + c]) =
                make_float4(tf32r(kv.x), tf32r(kv.y), tf32r(kv.z), tf32r(kv.w));
            float4 vv = *reinterpret_cast<const float4*>(base + 2048);
            *reinterpret_cast<float4*>(&Vs[row * SATT + c]) =
                make_float4(tf32r(vv.x), tf32r(vv.y), tf32r(vv.z), tf32r(vv.w));
        }
        __syncthreads();

        // ---- S = Q K^T (warp's 16 rows x 64 keys) ----
        float s[8][4];
        #pragma unroll
        for (int nt = 0; nt < 8; nt++)
            #pragma unroll
            for (int k = 0; k < 4; k++) s[nt][k] = 0.f;

        #pragma unroll
        for (int ks = 0; ks < 8; ks++) {
            uint32_t af[4];
            const uint32_t* pa = uQ + (mbase + gr) * SATT + ks * 8 + ctg;
            af[0] = pa[0];
            af[1] = pa[8 * SATT];
            af[2] = pa[4];
            af[3] = pa[8 * SATT + 4];
            #pragma unroll
            for (int nt = 0; nt < 8; nt++) {
                uint32_t bf[2];
                const uint32_t* pb = uK + (nt * 8 + gr) * SATT + ks * 8 + ctg;
                bf[0] = pb[0];
                bf[1] = pb[4];
                mma_tf32(s[nt], af, bf);
            }
        }

        // ---- online softmax (rows gr and gr+8 of warp band) ----
        float mx0 = -1e30f, mx1 = -1e30f;
        #pragma unroll
        for (int nt = 0; nt < 8; nt++) {
            s[nt][0] *= 0.125f; s[nt][1] *= 0.125f;
            s[nt][2] *= 0.125f; s[nt][3] *= 0.125f;
            mx0 = fmaxf(mx0, fmaxf(s[nt][0], s[nt][1]));
            mx1 = fmaxf(mx1, fmaxf(s[nt][2], s[nt][3]));
        }
        mx0 = fmaxf(mx0, __shfl_xor_sync(0xffffffffu, mx0, 1));
        mx0 = fmaxf(mx0, __shfl_xor_sync(0xffffffffu, mx0, 2));
        mx1 = fmaxf(mx1, __shfl_xor_sync(0xffffffffu, mx1, 1));
        mx1 = fmaxf(mx1, __shfl_xor_sync(0xffffffffu, mx1, 2));

        float mn0 = fmaxf(m0, mx0), mn1 = fmaxf(m1, mx1);
        float corr0 = __expf(m0 - mn0), corr1 = __expf(m1 - mn1);
        float sum0 = 0.f, sum1 = 0.f;
        #pragma unroll
        for (int nt = 0; nt < 8; nt++) {
            s[nt][0] = __expf(s[nt][0] - mn0);
            s[nt][1] = __expf(s[nt][1] - mn0);
            s[nt][2] = __expf(s[nt][2] - mn1);
            s[nt][3] = __expf(s[nt][3] - mn1);
            sum0 += s[nt][0] + s[nt][1];
            sum1 += s[nt][2] + s[nt][3];
        }
        sum0 += __shfl_xor_sync(0xffffffffu, sum0, 1);
        sum0 += __shfl_xor_sync(0xffffffffu, sum0, 2);
        sum1 += __shfl_xor_sync(0xffffffffu, sum1, 1);
        sum1 += __shfl_xor_sync(0xffffffffu, sum1, 2);

        l0 = l0 * corr0 + sum0;  m0 = mn0;
        l1 = l1 * corr1 + sum1;  m1 = mn1;

        #pragma unroll
        for (int nt = 0; nt < 8; nt++) {
            o[nt][0] *= corr0; o[nt][1] *= corr0;
            o[nt][2] *= corr1; o[nt][3] *= corr1;
        }

        // ---- store P (warp-private rows) ----
        #pragma unroll
        for (int nt = 0; nt < 8; nt++) {
            *reinterpret_cast<float2*>(&Ps[(mbase + gr) * SATT + nt * 8 + 2 * ctg]) =
                make_float2(tf32r(s[nt][0]), tf32r(s[nt][1]));
            *reinterpret_cast<float2*>(&Ps[(mbase + gr + 8) * SATT + nt * 8 + 2 * ctg]) =
                make_float2(tf32r(s[nt][2]), tf32r(s[nt][3]));
        }
        __syncwarp();

        // ---- O += P V ----
        #pragma unroll
        for (int ks = 0; ks < 8; ks++) {
            uint32_t af[4];
            const uint32_t* pa = uP + (mbase + gr) * SATT + ks * 8 + ctg;
            af[0] = pa[0];
            af[1] = pa[8 * SATT];
            af[2] = pa[4];
            af[3] = pa[8 * SATT + 4];
            #pragma unroll
            for (int nt = 0; nt < 8; nt++) {
                uint32_t bf[2];
                const uint32_t* pb = uV + (ks * 8 + ctg) * SATT + nt * 8 + gr;
                bf[0] = pb[0];
                bf[1] = pb[4 * SATT];
                mma_tf32(o[nt], af, bf);
            }
        }
    }

    // ---- final normalize + store ----
    const float inv0 = 1.0f / l0, inv1 = 1.0f / l1;
    const int row0 = tok0 + qb * 64 + mbase + gr;
    #pragma unroll
    for (int nt = 0; nt < 8; nt++) {
        const int col = h * 64 + nt * 8 + 2 * ctg;
        *reinterpret_cast<float2*>(out + (size_t)row0 * WIDTH + col) =
            make_float2(o[nt][0] * inv0, o[nt][1] * inv0);
        *reinterpret_cast<float2*>(out + (size_t)(row0 + 8) * WIDTH + col) =
            make_float2(o[nt][2] * inv1, o[nt][3] * inv1);
    }
}

// ---------------------------------------------------------------------------
// Launch
// ---------------------------------------------------------------------------
extern "C" void kernel_launch(void* const* d_in, const int* in_sizes, int n_in,
                              void* d_out, int out_size) {
    const float* x      = (const float*)d_in[0];
    const float* ln1_g  = (const float*)d_in[1];
    const float* ln1_b  = (const float*)d_in[2];
    const float* w_qkv  = (const float*)d_in[3];
    const float* w_proj = (const float*)d_in[4];
    const float* b_proj = (const float*)d_in[5];
    const float* ln2_g  = (const float*)d_in[6];
    const float* ln2_b  = (const float*)d_in[7];
    const float* w_fc1  = (const float*)d_in[8];
    const float* b_fc1  = (const float*)d_in[9];
    const float* w_fc2  = (const float*)d_in[10];
    const float* b_fc2  = (const float*)d_in[11];
    float* out = (float*)d_out;

    void *ph, *pqkv, *pattn, *px1, *pfc1;
    cudaGetSymbolAddress(&ph,    g_h);
    cudaGetSymbolAddress(&pqkv,  g_qkv);
    cudaGetSymbolAddress(&pattn, g_attn);
    cudaGetSymbolAddress(&px1,   g_x1);
    cudaGetSymbolAddress(&pfc1,  g_fc1);
    float* hbuf  = (float*)ph;
    float* qkvb  = (float*)pqkv;
    float* attnb = (float*)pattn;
    float* x1b   = (float*)px1;
    float* fc1b  = (float*)pfc1;

    cudaFuncSetAttribute(gemm_tc<0>, cudaFuncAttributeMaxDynamicSharedMemorySize, GEMM_SMEM_BYTES);
    cudaFuncSetAttribute(gemm_tc<1>, cudaFuncAttributeMaxDynamicSharedMemorySize, GEMM_SMEM_BYTES);
    cudaFuncSetAttribute(gemm_tc<2>, cudaFuncAttributeMaxDynamicSharedMemorySize, GEMM_SMEM_BYTES);
    cudaFuncSetAttribute(attn_tc,    cudaFuncAttributeMaxDynamicSharedMemorySize, ATTN_SMEM_BYTES);

    // 1) LN1
    ln_kernel<<<MTOK, 256>>>(x, ln1_g, ln1_b, hbuf);

    // 2) qkv = h @ w_qkv   [4096,1024]@[1024,3072]
    {
        dim3 grid(3 * WIDTH / 128, MTOK / 128);
        gemm_tc<0><<<grid, 256, GEMM_SMEM_BYTES>>>(MTOK, 3 * WIDTH, WIDTH,
                                                   hbuf, w_qkv, nullptr, nullptr, qkvb);
    }

    // 3) attention
    {
        dim3 grid(SEQ / 64, 2 * HEADS);
        attn_tc<<<grid, 128, ATTN_SMEM_BYTES>>>(qkvb, attnb);
    }

    // 4) x1 = x + attn @ w_proj + b_proj
    {
        dim3 grid(WIDTH / 128, MTOK / 128);
        gemm_tc<1><<<grid, 256, GEMM_SMEM_BYTES>>>(MTOK, WIDTH, WIDTH,
                                                   attnb, w_proj, b_proj, x, x1b);
    }

    // 5) LN2
    ln_kernel<<<MTOK, 256>>>(x1b, ln2_g, ln2_b, hbuf);

    // 6) fc1 = gelu(h @ w_fc1 + b_fc1)
    {
        dim3 grid(HIDDEN / 128, MTOK / 128);
        gemm_tc<2><<<grid, 256, GEMM_SMEM_BYTES>>>(MTOK, HIDDEN, WIDTH,
                                                   hbuf, w_fc1, b_fc1, nullptr, fc1b);
    }

    // 7) out = x1 + fc1 @ w_fc2 + b_fc2
    {
        dim3 grid(WIDTH / 128, MTOK / 128);
        gemm_tc<1><<<grid, 256, GEMM_SMEM_BYTES>>>(MTOK, WIDTH, HIDDEN,
                                                   fc1b, w_fc2, b_fc2, x1b, out);
    }
}

// round 4
// speedup vs baseline: 3.6276x; 1.2631x over previous
#include <cuda_runtime.h>
#include <cuda_bf16.h>
#include <math.h>
#include <stdint.h>

#define MTOK   4096
#define WIDTH  1024
#define HEADS  16
#define HDIM   64
#define HIDDEN 4096
#define SEQ    2048

__device__ float g_h   [MTOK * WIDTH];
__device__ float g_qkv [MTOK * 3 * WIDTH];
__device__ float g_attn[MTOK * WIDTH];
__device__ float g_x1  [MTOK * WIDTH];
__device__ float g_fc1 [MTOK * HIDDEN];
__device__ float g_wqkv_r [WIDTH * 3 * WIDTH];
__device__ float g_wproj_r[WIDTH * WIDTH];
__device__ float g_wfc1_r [WIDTH * HIDDEN];
__device__ float g_wfc2_r [HIDDEN * WIDTH];

__device__ __forceinline__ float warp_sum(float v) {
    #pragma unroll
    for (int o = 16; o > 0; o >>= 1) v += __shfl_xor_sync(0xffffffffu, v, o);
    return v;
}

__device__ __forceinline__ float tf32r(float x) {
    uint32_t u;
    asm("cvt.rna.tf32.f32 %0, %1;" : "=r"(u) : "f"(x));
    return __uint_as_float(u);
}

__device__ __forceinline__ void mma_tf32(float c[4], const uint32_t a[4], const uint32_t b[2]) {
    asm volatile(
        "mma.sync.aligned.m16n8k8.row.col.f32.tf32.tf32.f32 "
        "{%0,%1,%2,%3}, {%4,%5,%6,%7}, {%8,%9}, {%0,%1,%2,%3};\n"
        : "+f"(c[0]), "+f"(c[1]), "+f"(c[2]), "+f"(c[3])
        : "r"(a[0]), "r"(a[1]), "r"(a[2]), "r"(a[3]),
          "r"(b[0]), "r"(b[1]));
}

__device__ __forceinline__ void cp_async16(uint32_t s, const void* g) {
    asm volatile("cp.async.cg.shared.global [%0], [%1], 16;\n" :: "r"(s), "l"(g));
}
__device__ __forceinline__ void cp_commit() {
    asm volatile("cp.async.commit_group;\n" ::: "memory");
}
template <int N>
__device__ __forceinline__ void cp_wait() {
    asm volatile("cp.async.wait_group %0;\n" :: "n"(N) : "memory");
}

__device__ __forceinline__ float gelu_exact(float x) {
    return 0.5f * x * (1.0f + erff(x * 0.7071067811865476f));
}

__global__ void round_tf32_kernel(const float* __restrict__ in,
                                  float* __restrict__ out, int n4) {
    int i = blockIdx.x * blockDim.x + threadIdx.x;
    if (i < n4) {
        float4 v = reinterpret_cast<const float4*>(in)[i];
        reinterpret_cast<float4*>(out)[i] =
            make_float4(tf32r(v.x), tf32r(v.y), tf32r(v.z), tf32r(v.w));
    }
}

__global__ void ln_kernel(const float* __restrict__ x,
                          const float* __restrict__ g,
                          const float* __restrict__ b,
                          float* __restrict__ out) {
    int row = blockIdx.x;
    int t   = threadIdx.x;
    const float4* xr = reinterpret_cast<const float4*>(x + (size_t)row * WIDTH);
    float4 v = xr[t];
    float s  = v.x + v.y + v.z + v.w;
    float ss = v.x*v.x + v.y*v.y + v.z*v.z + v.w*v.w;

    __shared__ float red_s[8], red_ss[8];
    float ws = warp_sum(s), wss = warp_sum(ss);
    int wid = t >> 5, lid = t & 31;
    if (lid == 0) { red_s[wid] = ws; red_ss[wid] = wss; }
    __syncthreads();
    if (wid == 0) {
        float a  = (lid < 8) ? red_s[lid]  : 0.f;
        float a2 = (lid < 8) ? red_ss[lid] : 0.f;
        a  = warp_sum(a);
        a2 = warp_sum(a2);
        if (lid == 0) { red_s[0] = a; red_ss[0] = a2; }
    }
    __syncthreads();
    float mu  = red_s[0]  * (1.0f / WIDTH);
    float var = red_ss[0] * (1.0f / WIDTH) - mu * mu;
    float rs  = rsqrtf(var + 1e-5f);

    const float4* g4 = reinterpret_cast<const float4*>(g);
    const float4* b4 = reinterpret_cast<const float4*>(b);
    float4 gg = g4[t], bb = b4[t];
    float4 o;
    o.x = tf32r((v.x - mu) * rs * gg.x + bb.x);
    o.y = tf32r((v.y - mu) * rs * gg.y + bb.y);
    o.z = tf32r((v.z - mu) * rs * gg.z + bb.z);
    o.w = tf32r((v.w - mu) * rs * gg.w + bb.w);
    reinterpret_cast<float4*>(out + (size_t)row * WIDTH)[t] = o;
}

#define SA 36
#define SB 136
#define AS_FLOATS (128 * SA)
#define BS_FLOATS (32 * SB)
#define STAGE_FLOATS (AS_FLOATS + BS_FLOATS)
#define NSTAGE 3
#define GEMM_SMEM_BYTES (NSTAGE * STAGE_FLOATS * 4)

template <int OP, int ROUND_OUT>
__global__ void __launch_bounds__(256, 2)
gemm_tc(int M, int N, int K,
        const float* __restrict__ A,
        const float* __restrict__ B,
        const float* __restrict__ bias,
        const float* __restrict__ res,
        float* __restrict__ C) {
    extern __shared__ float sm[];

    const int tid     = threadIdx.x;
    const int warpId  = tid >> 5;
    const int lane    = tid & 31;
    const int gr      = lane >> 2;
    const int ctg     = lane & 3;
    const int warpRow = warpId >> 2;
    const int warpCol = warpId & 3;

    const int cRow = blockIdx.y;
    const int cCol = blockIdx.x;

    const float* Ablk = A + (size_t)cRow * 128 * K;
    const float* Bblk = B + cCol * 128;

    const uint32_t smBase = (uint32_t)__cvta_generic_to_shared(sm);

    auto load_stage = [&](int stg, int kb) {
        const uint32_t stageA = smBase + (uint32_t)(stg * STAGE_FLOATS) * 4u;
        const uint32_t stageB = stageA + (uint32_t)AS_FLOATS * 4u;
        const int kOff = kb << 5;
        #pragma unroll
        for (int i = 0; i < 4; i++) {
            int aIdx = tid + i * 256;
            int ar = aIdx >> 3, ac = (aIdx & 7) << 2;
            cp_async16(stageA + (uint32_t)(ar * SA + ac) * 4u,
                       Ablk + (size_t)ar * K + kOff + ac);
            int bIdx = tid + i * 256;
            int br = bIdx >> 5, bc = (bIdx & 31) << 2;
            cp_async16(stageB + (uint32_t)(br * SB + bc) * 4u,
                       Bblk + (size_t)(kOff + br) * N + bc);
        }
    };

    float acc[4][4][4];
    #pragma unroll
    for (int i = 0; i < 4; i++)
        #pragma unroll
        for (int j = 0; j < 4; j++)
            #pragma unroll
            for (int k = 0; k < 4; k++) acc[i][j][k] = 0.f;

    const int nChunk = K >> 5;

    load_stage(0, 0); cp_commit();
    load_stage(1, 1); cp_commit();
    cp_wait<1>();
    __syncthreads();

    for (int kb = 0; kb < nChunk; kb++) {
        const int cur = kb % NSTAGE;
        if (kb + 2 < nChunk) load_stage((kb + 2) % NSTAGE, kb + 2);
        cp_commit();

        const uint32_t* uAs = reinterpret_cast<const uint32_t*>(sm + cur * STAGE_FLOATS);
        const uint32_t* uBs = uAs + AS_FLOATS;

        #pragma unroll
        for (int ks = 0; ks < 4; ks++) {
            uint32_t af[4][4];
            #pragma unroll
            for (int mt = 0; mt < 4; mt++) {
                int m0 = warpRow * 64 + mt * 16 + gr;
                const uint32_t* pa = uAs + m0 * SA + ks * 8 + ctg;
                af[mt][0] = pa[0];
                af[mt][1] = pa[8 * SA];
                af[mt][2] = pa[4];
                af[mt][3] = pa[8 * SA + 4];
            }
            uint32_t bf[4][2];
            #pragma unroll
            for (int nt = 0; nt < 4; nt++) {
                int nb = warpCol * 32 + nt * 8 + gr;
                const uint32_t* pb = uBs + (ks * 8 + ctg) * SB + nb;
                bf[nt][0] = pb[0];
                bf[nt][1] = pb[4 * SB];
            }
            #pragma unroll
            for (int mt = 0; mt < 4; mt++)
                #pragma unroll
                for (int nt = 0; nt < 4; nt++)
                    mma_tf32(acc[mt][nt], af[mt], bf[nt]);
        }

        cp_wait<1>();
        __syncthreads();
    }

    #pragma unroll
    for (int mt = 0; mt < 4; mt++) {
        #pragma unroll
        for (int rr = 0; rr < 2; rr++) {
            const int row = cRow * 128 + warpRow * 64 + mt * 16 + gr + rr * 8;
            #pragma unroll
            for (int nt = 0; nt < 4; nt++) {
                const int col = cCol * 128 + warpCol * 32 + nt * 8 + 2 * ctg;
                float v0 = acc[mt][nt][rr * 2 + 0];
                float v1 = acc[mt][nt][rr * 2 + 1];
                if (OP == 1) {
                    float2 bi = *reinterpret_cast<const float2*>(bias + col);
                    float2 rv = *reinterpret_cast<const float2*>(res + (size_t)row * N + col);
                    v0 += bi.x + rv.x;
                    v1 += bi.y + rv.y;
                } else if (OP == 2) {
                    float2 bi = *reinterpret_cast<const float2*>(bias + col);
                    v0 = gelu_exact(v0 + bi.x);
                    v1 = gelu_exact(v1 + bi.y);
                }
                if (ROUND_OUT) { v0 = tf32r(v0); v1 = tf32r(v1); }
                *reinterpret_cast<float2*>(C + (size_t)row * N + col) = make_float2(v0, v1);
            }
        }
    }
}

#define SATT 68
#define ATT_TILE (64 * SATT)
#define ATTN_SMEM_BYTES (4 * ATT_TILE * 4)

__global__ void __launch_bounds__(128)
attn_tc(const float* __restrict__ qkv, float* __restrict__ out) {
    extern __shared__ float sm[];
    float* Qs = sm;
    float* Ks = sm + ATT_TILE;
    float* Vs = sm + 2 * ATT_TILE;
    float* Ps = sm + 3 * ATT_TILE;
    const uint32_t* uQ = reinterpret_cast<const uint32_t*>(Qs);
    const uint32_t* uK = reinterpret_cast<const uint32_t*>(Ks);
    const uint32_t* uV = reinterpret_cast<const uint32_t*>(Vs);
    const uint32_t* uP = reinterpret_cast<const uint32_t*>(Ps);

    const int t     = threadIdx.x;
    const int warp  = t >> 5;
    const int lane  = t & 31;
    const int gr    = lane >> 2;
    const int ctg   = lane & 3;
    const int mbase = warp * 16;

    const int qb = blockIdx.x;
    const int bh = blockIdx.y;
    const int bb = bh >> 4;
    const int h  = bh & 15;
    const int tok0 = bb * SEQ;

    #pragma unroll
    for (int i = 0; i < 8; i++) {
        int idx = t + i * 128;
        int row = idx >> 4;
        int c   = (idx & 15) << 2;
        float4 v = *reinterpret_cast<const float4*>(
            qkv + (size_t)(tok0 + qb * 64 + row) * 3072 + h * 64 + c);
        *reinterpret_cast<float4*>(&Qs[row * SATT + c]) =
            make_float4(tf32r(v.x), tf32r(v.y), tf32r(v.z), tf32r(v.w));
    }

    float m0 = -1e30f, m1 = -1e30f, l0 = 0.f, l1 = 0.f;
    float o[8][4];
    #pragma unroll
    for (int nt = 0; nt < 8; nt++)
        #pragma unroll
        for (int k = 0; k < 4; k++) o[nt][k] = 0.f;

    for (int kb = 0; kb < SEQ / 64; kb++) {
        __syncthreads();

        #pragma unroll
        for (int i = 0; i < 8; i++) {
            int idx = t + i * 128;
            int row = idx >> 4;
            int c   = (idx & 15) << 2;
            const float* base = qkv + (size_t)(tok0 + kb * 64 + row) * 3072 + h * 64 + c;
            float4 kv = *reinterpret_cast<const float4*>(base + 1024);
            *reinterpret_cast<float4*>(&Ks[row * SATT + c]) =
                make_float4(tf32r(kv.x), tf32r(kv.y), tf32r(kv.z), tf32r(kv.w));
            float4 vv = *reinterpret_cast<const float4*>(base + 2048);
            *reinterpret_cast<float4*>(&Vs[row * SATT + c]) =
                make_float4(tf32r(vv.x), tf32r(vv.y), tf32r(vv.z), tf32r(vv.w));
        }
        __syncthreads();

        float s[8][4];
        #pragma unroll
        for (int nt = 0; nt < 8; nt++)
            #pragma unroll
            for (int k = 0; k < 4; k++) s[nt][k] = 0.f;

        #pragma unroll
        for (int ks = 0; ks < 8; ks++) {
            uint32_t af[4];
            const uint32_t* pa = uQ + (mbase + gr) * SATT + ks * 8 + ctg;
            af[0] = pa[0];
            af[1] = pa[8 * SATT];
            af[2] = pa[4];
            af[3] = pa[8 * SATT + 4];
            #pragma unroll
            for (int nt = 0; nt < 8; nt++) {
                uint32_t bf[2];
                const uint32_t* pb = uK + (nt * 8 + gr) * SATT + ks * 8 + ctg;
                bf[0] = pb[0];
                bf[1] = pb[4];
                mma_tf32(s[nt], af, bf);
            }
        }

        float mx0 = -1e30f, mx1 = -1e30f;
        #pragma unroll
        for (int nt = 0; nt < 8; nt++) {
            s[nt][0] *= 0.125f; s[nt][1] *= 0.125f;
            s[nt][2] *= 0.125f; s[nt][3] *= 0.125f;
            mx0 = fmaxf(mx0, fmaxf(s[nt][0], s[nt][1]));
            mx1 = fmaxf(mx1, fmaxf(s[nt][2], s[nt][3]));
        }
        mx0 = fmaxf(mx0, __shfl_xor_sync(0xffffffffu, mx0, 1));
        mx0 = fmaxf(mx0, __shfl_xor_sync(0xffffffffu, mx0, 2));
        mx1 = fmaxf(mx1, __shfl_xor_sync(0xffffffffu, mx1, 1));
        mx1 = fmaxf(mx1, __shfl_xor_sync(0xffffffffu, mx1, 2));

        float mn0 = fmaxf(m0, mx0), mn1 = fmaxf(m1, mx1);
        float corr0 = __expf(m0 - mn0), corr1 = __expf(m1 - mn1);
        float sum0 = 0.f, sum1 = 0.f;
        #pragma unroll
        for (int nt = 0; nt < 8; nt++) {
            s[nt][0] = __expf(s[nt][0] - mn0);
            s[nt][1] = __expf(s[nt][1] - mn0);
            s[nt][2] = __expf(s[nt][2] - mn1);
            s[nt][3] = __expf(s[nt][3] - mn1);
            sum0 += s[nt][0] + s[nt][1];
            sum1 += s[nt][2] + s[nt][3];
        }
        sum0 += __shfl_xor_sync(0xffffffffu, sum0, 1);
        sum0 += __shfl_xor_sync(0xffffffffu, sum0, 2);
        sum1 += __shfl_xor_sync(0xffffffffu, sum1, 1);
        sum1 += __shfl_xor_sync(0xffffffffu, sum1, 2);

        l0 = l0 * corr0 + sum0;  m0 = mn0;
        l1 = l1 * corr1 + sum1;  m1 = mn1;

        #pragma unroll
        for (int nt = 0; nt < 8; nt++) {
            o[nt][0] *= corr0; o[nt][1] *= corr0;
            o[nt][2] *= corr1; o[nt][3] *= corr1;
        }

        #pragma unroll
        for (int nt = 0; nt < 8; nt++) {
            *reinterpret_cast<float2*>(&Ps[(mbase + gr) * SATT + nt * 8 + 2 * ctg]) =
                make_float2(tf32r(s[nt][0]), tf32r(s[nt][1]));
            *reinterpret_cast<float2*>(&Ps[(mbase + gr + 8) * SATT + nt * 8 + 2 * ctg]) =
                make_float2(tf32r(s[nt][2]), tf32r(s[nt][3]));
        }
        __syncwarp();

        #pragma unroll
        for (int ks = 0; ks < 8; ks++) {
            uint32_t af[4];
            const uint32_t* pa = uP + (mbase + gr) * SATT + ks * 8 + ctg;
            af[0] = pa[0];
            af[1] = pa[8 * SATT];
            af[2] = pa[4];
            af[3] = pa[8 * SATT + 4];
            #pragma unroll
            for (int nt = 0; nt < 8; nt++) {
                uint32_t bf[2];
                const uint32_t* pb = uV + (ks * 8 + ctg) * SATT + nt * 8 + gr;
                bf[0] = pb[0];
                bf[1] = pb[4 * SATT];
                mma_tf32(o[nt], af, bf);
            }
        }
    }

    const float inv0 = 1.0f / l0, inv1 = 1.0f / l1;
    const int row0 = tok0 + qb * 64 + mbase + gr;
    #pragma unroll
    for (int nt = 0; nt < 8; nt++) {
        const int col = h * 64 + nt * 8 + 2 * ctg;
        *reinterpret_cast<float2*>(out + (size_t)row0 * WIDTH + col) =
            make_float2(tf32r(o[nt][0] * inv0), tf32r(o[nt][1] * inv0));
        *reinterpret_cast<float2*>(out + (size_t)(row0 + 8) * WIDTH + col) =
            make_float2(tf32r(o[nt][2] * inv1), tf32r(o[nt][3] * inv1));
    }
}

extern "C" void kernel_launch(void* const* d_in, const int* in_sizes, int n_in,
                              void* d_out, int out_size) {
    const float* x      = (const float*)d_in[0];
    const float* ln1_g  = (const float*)d_in[1];
    const float* ln1_b  = (const float*)d_in[2];
    const float* w_qkv  = (const float*)d_in[3];
    const float* w_proj = (const float*)d_in[4];
    const float* b_proj = (const float*)d_in[5];
    const float* ln2_g  = (const float*)d_in[6];
    const float* ln2_b  = (const float*)d_in[7];
    const float* w_fc1  = (const float*)d_in[8];
    const float* b_fc1  = (const float*)d_in[9];
    const float* w_fc2  = (const float*)d_in[10];
    const float* b_fc2  = (const float*)d_in[11];
    float* out = (float*)d_out;

    void *ph, *pqkv, *pattn, *px1, *pfc1, *pwq, *pwp, *pw1, *pw2;
    cudaGetSymbolAddress(&ph,    g_h);
    cudaGetSymbolAddress(&pqkv,  g_qkv);
    cudaGetSymbolAddress(&pattn, g_attn);
    cudaGetSymbolAddress(&px1,   g_x1);
    cudaGetSymbolAddress(&pfc1,  g_fc1);
    cudaGetSymbolAddress(&pwq,   g_wqkv_r);
    cudaGetSymbolAddress(&pwp,   g_wproj_r);
    cudaGetSymbolAddress(&pw1,   g_wfc1_r);
    cudaGetSymbolAddress(&pw2,   g_wfc2_r);
    float* hbuf  = (float*)ph;
    float* qkvb  = (float*)pqkv;
    float* attnb = (float*)pattn;
    float* x1b   = (float*)px1;
    float* fc1b  = (float*)pfc1;
    float* wqr   = (float*)pwq;
    float* wpr   = (float*)pwp;
    float* w1r   = (float*)pw1;
    float* w2r   = (float*)pw2;

    cudaFuncSetAttribute(gemm_tc<0,0>, cudaFuncAttributeMaxDynamicSharedMemorySize, GEMM_SMEM_BYTES);
    cudaFuncSetAttribute(gemm_tc<1,0>, cudaFuncAttributeMaxDynamicSharedMemorySize, GEMM_SMEM_BYTES);
    cudaFuncSetAttribute(gemm_tc<2,1>, cudaFuncAttributeMaxDynamicSharedMemorySize, GEMM_SMEM_BYTES);
    cudaFuncSetAttribute(attn_tc,      cudaFuncAttributeMaxDynamicSharedMemorySize, ATTN_SMEM_BYTES);

    // 0) round weights to tf32
    {
        int n;
        n = WIDTH * 3 * WIDTH / 4;  round_tf32_kernel<<<(n + 255) / 256, 256>>>(w_qkv, wqr, n);
        n = WIDTH * WIDTH / 4;      round_tf32_kernel<<<(n + 255) / 256, 256>>>(w_proj, wpr, n);
        n = WIDTH * HIDDEN / 4;     round_tf32_kernel<<<(n + 255) / 256, 256>>>(w_fc1, w1r, n);
        n = HIDDEN * WIDTH / 4;     round_tf32_kernel<<<(n + 255) / 256, 256>>>(w_fc2, w2r, n);
    }

    // 1) LN1 (rounded output)
    ln_kernel<<<MTOK, 256>>>(x, ln1_g, ln1_b, hbuf);

    // 2) qkv = h @ w_qkv
    {
        dim3 grid(3 * WIDTH / 128, MTOK / 128);
        gemm_tc<0,0><<<grid, 256, GEMM_SMEM_BYTES>>>(MTOK, 3 * WIDTH, WIDTH,
                                                     hbuf, wqr, nullptr, nullptr, qkvb);
    }

    // 3) attention (rounded output)
    {
        dim3 grid(SEQ / 64, 2 * HEADS);
        attn_tc<<<grid, 128, ATTN_SMEM_BYTES>>>(qkvb, attnb);
    }

    // 4) x1 = x + attn @ w_proj + b_proj
    {
        dim3 grid(WIDTH / 128, MTOK / 128);
        gemm_tc<1,0><<<grid, 256, GEMM_SMEM_BYTES>>>(MTOK, WIDTH, WIDTH,
                                                     attnb, wpr, b_proj, x, x1b);
    }

    // 5) LN2 (rounded output)
    ln_kernel<<<MTOK, 256>>>(x1b, ln2_g, ln2_b, hbuf);

    // 6) fc1 = gelu(h @ w_fc1 + b_fc1) (rounded output)
    {
        dim3 grid(HIDDEN / 128, MTOK / 128);
        gemm_tc<2,1><<<grid, 256, GEMM_SMEM_BYTES>>>(MTOK, HIDDEN, WIDTH,
                                                     hbuf, w1r, b_fc1, nullptr, fc1b);
    }

    // 7) out = x1 + fc1 @ w_fc2 + b_fc2
    {
        dim3 grid(WIDTH / 128, MTOK / 128);
        gemm_tc<1,0><<<grid, 256, GEMM_SMEM_BYTES>>>(MTOK, WIDTH, HIDDEN,
                                                     fc1b, w2r, b_fc2, x1b, out);
    }
}